// round 1
// baseline (speedup 1.0000x reference)
#include <cuda_runtime.h>
#include <math.h>

#define Hh   16
#define Dh   64
#define Bn   2
#define Sn   2048
#define Cn   1024
#define Mrows (Bn*Sn)          // 4096

// scratch (allocation-free rule: __device__ globals)
__device__ float g_q[(size_t)Bn*Hh*Sn*Dh];
__device__ float g_k[(size_t)Bn*Hh*Sn*Dh];
__device__ float g_v[(size_t)Bn*Hh*Sn*Dh];
__device__ float g_attn[(size_t)Mrows*Cn];

// ---------------------------------------------------------------------------
// Kernel 1: fused QKV projection.  out[b,h,s,d] = sum_c x[b,s,c] * W[h,c,d]
// GEMM M=4096, K=1024, N=1024 (H*D), grid.z picks q/k/v.
// 128x128 tile, BK=16, 256 threads, 8x8 per thread.
// ---------------------------------------------------------------------------
__global__ __launch_bounds__(256)
void proj_kernel(const float* __restrict__ X,
                 const float* __restrict__ Wq,
                 const float* __restrict__ Wk,
                 const float* __restrict__ Wv)
{
    const int z = blockIdx.z;
    const float* W = (z == 0) ? Wq : (z == 1) ? Wk : Wv;
    float* outp    = (z == 0) ? g_q : (z == 1) ? g_k : g_v;

    __shared__ float As[16][128];
    __shared__ float Bs[16][128];

    const int tid = threadIdx.x;
    const int m0 = blockIdx.y * 128;
    const int n0 = blockIdx.x * 128;
    const int ty = tid >> 4, tx = tid & 15;

    float acc[8][8];
    #pragma unroll
    for (int i = 0; i < 8; i++)
        #pragma unroll
        for (int j = 0; j < 8; j++) acc[i][j] = 0.f;

    for (int k0 = 0; k0 < Cn; k0 += 16) {
        #pragma unroll
        for (int t = 0; t < 2; t++) {
            int idx = tid + t * 256;            // 0..511 float4s
            int row = idx >> 2;                 // 0..127
            int kc  = (idx & 3) * 4;
            float4 v = *(const float4*)(X + (size_t)(m0 + row) * Cn + k0 + kc);
            As[kc + 0][row] = v.x; As[kc + 1][row] = v.y;
            As[kc + 2][row] = v.z; As[kc + 3][row] = v.w;
        }
        #pragma unroll
        for (int t = 0; t < 2; t++) {
            int idx = tid + t * 256;
            int kk = idx >> 5;                  // 0..15
            int nn = (idx & 31) * 4;            // 0..124
            int n  = n0 + nn;
            // W[h, c, d]  with  h = n>>6, d = n&63 (float4 stays within head)
            float4 v = *(const float4*)(W + ((size_t)(n >> 6) * Cn + (k0 + kk)) * Dh + (n & 63));
            *(float4*)&Bs[kk][nn] = v;
        }
        __syncthreads();
        #pragma unroll
        for (int kk = 0; kk < 16; kk++) {
            float a[8], b[8];
            *(float4*)&a[0] = *(const float4*)&As[kk][ty * 8];
            *(float4*)&a[4] = *(const float4*)&As[kk][ty * 8 + 4];
            *(float4*)&b[0] = *(const float4*)&Bs[kk][tx * 8];
            *(float4*)&b[4] = *(const float4*)&Bs[kk][tx * 8 + 4];
            #pragma unroll
            for (int i = 0; i < 8; i++)
                #pragma unroll
                for (int j = 0; j < 8; j++)
                    acc[i][j] = fmaf(a[i], b[j], acc[i][j]);
        }
        __syncthreads();
    }

    // epilogue: write to [b, h, s, d]
    #pragma unroll
    for (int i = 0; i < 8; i++) {
        int m  = m0 + ty * 8 + i;
        int b_ = m >> 11;           // / Sn
        int s  = m & (Sn - 1);
        #pragma unroll
        for (int j0 = 0; j0 < 8; j0 += 4) {
            int n  = n0 + tx * 8 + j0;
            int hh = n >> 6;
            int dd = n & 63;
            float4 w = make_float4(acc[i][j0], acc[i][j0 + 1], acc[i][j0 + 2], acc[i][j0 + 3]);
            *(float4*)(outp + (((size_t)b_ * Hh + hh) * Sn + s) * Dh + dd) = w;
        }
    }
}

// ---------------------------------------------------------------------------
// Kernel 2: causal flash attention.  Br=128 query rows per block, Bc=64 keys
// per inner tile, D=64.  Writes g_attn[b, s, h*64+d] (concat-heads layout).
// ---------------------------------------------------------------------------
#define BR 128
#define BC 64
#define FLASH_SMEM ((64*128 + 64*64 + 64*64 + 128*64) * 4)   // 96 KB

__global__ __launch_bounds__(256)
void flash_kernel()
{
    extern __shared__ float sm[];
    float* Qt = sm;                       // [64][128]  Qt[d][r]
    float* Kt = Qt + 64 * BR;             // [64][64]   Kt[d][c]
    float* Vs = Kt + 64 * BC;             // [64][64]   Vs[j][d]
    float* Ps = Vs + BC * Dh;             // [128][64]  Ps[r][j]

    const int tid = threadIdx.x;
    const int bh  = blockIdx.y;           // b*H + h
    const int qt  = blockIdx.x;
    const int qs0 = qt * BR;

    const float* Qb = g_q + (size_t)bh * Sn * Dh;
    const float* Kb = g_k + (size_t)bh * Sn * Dh;
    const float* Vb = g_v + (size_t)bh * Sn * Dh;

    // load Q tile transposed
    #pragma unroll
    for (int t = 0; t < 8; t++) {
        int idx = tid + t * 256;           // 0..2047 float4s
        int r = idx >> 4;
        int d = (idx & 15) * 4;
        float4 v = *(const float4*)(Qb + (size_t)(qs0 + r) * Dh + d);
        Qt[(d + 0) * BR + r] = v.x; Qt[(d + 1) * BR + r] = v.y;
        Qt[(d + 2) * BR + r] = v.z; Qt[(d + 3) * BR + r] = v.w;
    }

    const int ty = tid >> 4, tx = tid & 15;
    float o[8][4];
    float m_[8], l_[8];
    #pragma unroll
    for (int i = 0; i < 8; i++) {
        m_[i] = -1e30f; l_[i] = 0.f;
        #pragma unroll
        for (int j = 0; j < 4; j++) o[i][j] = 0.f;
    }

    const int ntiles = 2 * qt + 2;
    const float scale = 0.125f;            // 1/sqrt(64)

    for (int jt = 0; jt < ntiles; jt++) {
        const int ks0 = jt * BC;
        __syncthreads();                   // prev-iter Kt/Vs/Ps reads done
        #pragma unroll
        for (int t = 0; t < 4; t++) {
            int idx = tid + t * 256;       // 0..1023 float4s
            int r = idx >> 4;
            int d = (idx & 15) * 4;
            float4 kv = *(const float4*)(Kb + (size_t)(ks0 + r) * Dh + d);
            Kt[(d + 0) * BC + r] = kv.x; Kt[(d + 1) * BC + r] = kv.y;
            Kt[(d + 2) * BC + r] = kv.z; Kt[(d + 3) * BC + r] = kv.w;
            float4 vv = *(const float4*)(Vb + (size_t)(ks0 + r) * Dh + d);
            *(float4*)&Vs[r * Dh + d] = vv;
        }
        __syncthreads();

        // S = Q K^T
        float s_[8][4];
        #pragma unroll
        for (int i = 0; i < 8; i++)
            #pragma unroll
            for (int j = 0; j < 4; j++) s_[i][j] = 0.f;

        #pragma unroll 4
        for (int kk = 0; kk < 64; kk++) {
            float a[8], b[4];
            *(float4*)&a[0] = *(const float4*)&Qt[kk * BR + ty * 8];
            *(float4*)&a[4] = *(const float4*)&Qt[kk * BR + ty * 8 + 4];
            *(float4*)&b[0] = *(const float4*)&Kt[kk * BC + tx * 4];
            #pragma unroll
            for (int i = 0; i < 8; i++)
                #pragma unroll
                for (int j = 0; j < 4; j++)
                    s_[i][j] = fmaf(a[i], b[j], s_[i][j]);
        }

        const bool diag = (jt >= ntiles - 2);
        #pragma unroll
        for (int i = 0; i < 8; i++) {
            int qi = qs0 + ty * 8 + i;
            #pragma unroll
            for (int j = 0; j < 4; j++) {
                float v = s_[i][j] * scale;
                if (diag && (ks0 + tx * 4 + j > qi)) v = -1e30f;
                s_[i][j] = v;
            }
        }

        // online softmax
        #pragma unroll
        for (int i = 0; i < 8; i++) {
            float rm = fmaxf(fmaxf(s_[i][0], s_[i][1]), fmaxf(s_[i][2], s_[i][3]));
            #pragma unroll
            for (int off = 1; off < 16; off <<= 1)
                rm = fmaxf(rm, __shfl_xor_sync(0xffffffffu, rm, off));
            float mnew  = fmaxf(m_[i], rm);
            float alpha = __expf(m_[i] - mnew);
            m_[i] = mnew;
            float rs = 0.f;
            #pragma unroll
            for (int j = 0; j < 4; j++) {
                float p = __expf(s_[i][j] - mnew);
                s_[i][j] = p;
                rs += p;
            }
            l_[i] = l_[i] * alpha + rs;    // per-thread partial; reduced at end
            #pragma unroll
            for (int j = 0; j < 4; j++) o[i][j] *= alpha;
        }

        // stage P
        #pragma unroll
        for (int i = 0; i < 8; i++)
            *(float4*)&Ps[(ty * 8 + i) * BC + tx * 4] =
                make_float4(s_[i][0], s_[i][1], s_[i][2], s_[i][3]);
        __syncthreads();

        // O += P V
        #pragma unroll 8
        for (int j = 0; j < BC; j++) {
            float4 v4 = *(const float4*)&Vs[j * Dh + tx * 4];
            #pragma unroll
            for (int i = 0; i < 8; i++) {
                float pr = Ps[(ty * 8 + i) * BC + j];
                o[i][0] = fmaf(pr, v4.x, o[i][0]);
                o[i][1] = fmaf(pr, v4.y, o[i][1]);
                o[i][2] = fmaf(pr, v4.z, o[i][2]);
                o[i][3] = fmaf(pr, v4.w, o[i][3]);
            }
        }
    }

    // finish: reduce l across the 16 tx lanes, normalize, write
    const int b_ = bh / Hh, h_ = bh % Hh;
    #pragma unroll
    for (int i = 0; i < 8; i++) {
        float l = l_[i];
        #pragma unroll
        for (int off = 1; off < 16; off <<= 1)
            l += __shfl_xor_sync(0xffffffffu, l, off);
        float inv = 1.f / l;
        int r = qs0 + ty * 8 + i;
        float4 w = make_float4(o[i][0] * inv, o[i][1] * inv, o[i][2] * inv, o[i][3] * inv);
        *(float4*)(g_attn + ((size_t)(b_ * Sn + r)) * Cn + h_ * Dh + tx * 4) = w;
    }
}

// ---------------------------------------------------------------------------
// Kernel 3: output projection.  out = g_attn @ Wo + bo   (4096x1024x1024)
// ---------------------------------------------------------------------------
__global__ __launch_bounds__(256)
void outproj_kernel(const float* __restrict__ Wo,
                    const float* __restrict__ bo,
                    float* __restrict__ out)
{
    __shared__ float As[16][128];
    __shared__ float Bs[16][128];

    const int tid = threadIdx.x;
    const int m0 = blockIdx.y * 128;
    const int n0 = blockIdx.x * 128;
    const int ty = tid >> 4, tx = tid & 15;

    float acc[8][8];
    #pragma unroll
    for (int i = 0; i < 8; i++)
        #pragma unroll
        for (int j = 0; j < 8; j++) acc[i][j] = 0.f;

    for (int k0 = 0; k0 < Cn; k0 += 16) {
        #pragma unroll
        for (int t = 0; t < 2; t++) {
            int idx = tid + t * 256;
            int row = idx >> 2;
            int kc  = (idx & 3) * 4;
            float4 v = *(const float4*)(g_attn + (size_t)(m0 + row) * Cn + k0 + kc);
            As[kc + 0][row] = v.x; As[kc + 1][row] = v.y;
            As[kc + 2][row] = v.z; As[kc + 3][row] = v.w;
        }
        #pragma unroll
        for (int t = 0; t < 2; t++) {
            int idx = tid + t * 256;
            int kk = idx >> 5;
            int nn = (idx & 31) * 4;
            float4 v = *(const float4*)(Wo + (size_t)(k0 + kk) * Cn + n0 + nn);
            *(float4*)&Bs[kk][nn] = v;
        }
        __syncthreads();
        #pragma unroll
        for (int kk = 0; kk < 16; kk++) {
            float a[8], b[8];
            *(float4*)&a[0] = *(const float4*)&As[kk][ty * 8];
            *(float4*)&a[4] = *(const float4*)&As[kk][ty * 8 + 4];
            *(float4*)&b[0] = *(const float4*)&Bs[kk][tx * 8];
            *(float4*)&b[4] = *(const float4*)&Bs[kk][tx * 8 + 4];
            #pragma unroll
            for (int i = 0; i < 8; i++)
                #pragma unroll
                for (int j = 0; j < 8; j++)
                    acc[i][j] = fmaf(a[i], b[j], acc[i][j]);
        }
        __syncthreads();
    }

    float bb[8];
    #pragma unroll
    for (int j = 0; j < 8; j++) bb[j] = bo[n0 + tx * 8 + j];

    #pragma unroll
    for (int i = 0; i < 8; i++) {
        int m = m0 + ty * 8 + i;
        #pragma unroll
        for (int j0 = 0; j0 < 8; j0 += 4) {
            float4 w = make_float4(acc[i][j0] + bb[j0], acc[i][j0 + 1] + bb[j0 + 1],
                                   acc[i][j0 + 2] + bb[j0 + 2], acc[i][j0 + 3] + bb[j0 + 3]);
            *(float4*)(out + (size_t)m * Cn + n0 + tx * 8 + j0) = w;
        }
    }
}

// ---------------------------------------------------------------------------
extern "C" void kernel_launch(void* const* d_in, const int* in_sizes, int n_in,
                              void* d_out, int out_size)
{
    (void)in_sizes; (void)n_in; (void)out_size;
    const float* x  = (const float*)d_in[0];
    const float* Wq = (const float*)d_in[1];
    const float* Wk = (const float*)d_in[2];
    const float* Wv = (const float*)d_in[3];
    const float* Wo = (const float*)d_in[4];
    const float* bo = (const float*)d_in[5];
    float* out = (float*)d_out;

    cudaFuncSetAttribute(flash_kernel, cudaFuncAttributeMaxDynamicSharedMemorySize, FLASH_SMEM);

    proj_kernel<<<dim3(Cn / 128, Mrows / 128, 3), 256>>>(x, Wq, Wk, Wv);
    flash_kernel<<<dim3(Sn / BR, Bn * Hh), 256, FLASH_SMEM>>>();
    outproj_kernel<<<dim3(Cn / 128, Mrows / 128), 256>>>(Wo, bo, out);
}